// round 1
// baseline (speedup 1.0000x reference)
#include <cuda_runtime.h>
#include <math.h>

// ---------------- problem constants ----------------
#define BATCH 16
#define HH 56
#define WW 56
#define NTOK 3136            // 56*56
#define CDIM 384
#define HEADS 12
#define HD 32
#define WS 7
#define LWIN 49
#define NWIN 64              // windows per image (8x8)
#define HID 1536
#define MTOT 50176           // BATCH*NTOK = 392*128

// ---------------- scratch (static device memory; no allocations) ----------------
__device__ float g_xw  [(size_t)MTOT * CDIM];   // LN1 + shifted window partition
__device__ float g_qkv [(size_t)MTOT * 3 * CDIM];
__device__ float g_attn[(size_t)MTOT * CDIM];   // attention output (window order)
__device__ float g_x2  [(size_t)MTOT * CDIM];   // after attn residual (spatial order)
__device__ float g_xn2 [(size_t)MTOT * CDIM];   // LN2 output
__device__ float g_h1  [(size_t)MTOT * HID];    // fc1 output
__device__ float g_h2  [(size_t)MTOT * HID];    // dwconv+gelu output

// window-order row -> spatial row (window reverse, NO un-shift, per reference)
__device__ __forceinline__ int map_win_to_spatial(int row)
{
    int b  = row / NTOK;
    int t  = row - b * NTOK;
    int wi = t / LWIN;
    int p  = t - wi * LWIN;
    int pr = p / WS;
    int pc = p - pr * WS;
    int h  = (wi >> 3) * WS + pr;
    int w  = (wi & 7)  * WS + pc;
    return b * NTOK + h * WW + w;
}

// ---------------- LayerNorm (optionally fused with shift + window partition) ----------------
template <bool SHIFT>
__global__ __launch_bounds__(128)
void ln_kernel(const float* __restrict__ x, const float* __restrict__ g,
               const float* __restrict__ b, float* __restrict__ out)
{
    int row = blockIdx.x;          // output row (window order if SHIFT, spatial else)
    int srow;
    if (SHIFT) {
        int bb = row / NTOK;
        int t  = row - bb * NTOK;
        int wi = t / LWIN;
        int p  = t - wi * LWIN;
        int pr = p / WS;
        int pc = p - pr * WS;
        int h  = (wi >> 3) * WS + pr + 3; if (h >= HH) h -= HH;   // roll(-3)
        int w  = (wi & 7)  * WS + pc + 3; if (w >= WW) w -= WW;
        srow = bb * NTOK + h * WW + w;
    } else {
        srow = row;
    }
    const float* xr = x + (size_t)srow * CDIM;
    int tid = threadIdx.x;
    float v0 = xr[tid], v1 = xr[tid + 128], v2 = xr[tid + 256];
    float s  = v0 + v1 + v2;
    float ss = v0 * v0 + v1 * v1 + v2 * v2;
#pragma unroll
    for (int off = 16; off; off >>= 1) {
        s  += __shfl_xor_sync(0xffffffffu, s,  off);
        ss += __shfl_xor_sync(0xffffffffu, ss, off);
    }
    __shared__ float rs[4], rq[4];
    __shared__ float mean_s, inv_s;
    if ((tid & 31) == 0) { rs[tid >> 5] = s; rq[tid >> 5] = ss; }
    __syncthreads();
    if (tid == 0) {
        float S = rs[0] + rs[1] + rs[2] + rs[3];
        float Q = rq[0] + rq[1] + rq[2] + rq[3];
        float m = S * (1.0f / CDIM);
        float var = Q * (1.0f / CDIM) - m * m;
        mean_s = m;
        inv_s  = rsqrtf(var + 1e-5f);
    }
    __syncthreads();
    float m = mean_s, inv = inv_s;
    float* o = out + (size_t)row * CDIM;
    o[tid]       = (v0 - m) * inv * g[tid]       + b[tid];
    o[tid + 128] = (v1 - m) * inv * g[tid + 128] + b[tid + 128];
    o[tid + 256] = (v2 - m) * inv * g[tid + 256] + b[tid + 256];
}

// ---------------- fp32 SIMT GEMM: C(MxN) = A(MxK,row) * B(KxN,row) ----------------
// MODE 0: plain    MODE 1: +bias    MODE 2: +bias, scatter rows (win->spatial) + residual
// MODE 3: +bias + residual (same row)
// Requires M%128==0, N%128==0, K%8==0 (always true here).
template <int MODE>
__global__ __launch_bounds__(256)
void sgemm128(const float* __restrict__ A, const float* __restrict__ B,
              float* __restrict__ C, const float* __restrict__ bias,
              const float* __restrict__ resid, int K, int N)
{
    __shared__ float As[8][128];
    __shared__ float Bs[8][128];

    const int tid = threadIdx.x;
    const int bm  = blockIdx.y << 7;
    const int bn  = blockIdx.x << 7;
    const int tm  = (tid >> 4) << 3;
    const int tn  = (tid & 15) << 3;
    const int arow = tid >> 1;
    const int acol = (tid & 1) << 2;
    const int brow = tid >> 5;
    const int bcol = (tid & 31) << 2;

    const float* Apt = A + (size_t)(bm + arow) * K + acol;
    const float* Bpt = B + (size_t)brow * N + bn + bcol;

    float acc[8][8];
#pragma unroll
    for (int i = 0; i < 8; i++)
#pragma unroll
        for (int j = 0; j < 8; j++) acc[i][j] = 0.0f;

    for (int k0 = 0; k0 < K; k0 += 8) {
        float4 a = *(const float4*)(Apt + k0);
        float4 bb = *(const float4*)(Bpt + (size_t)k0 * N);
        __syncthreads();
        As[acol    ][arow] = a.x;
        As[acol + 1][arow] = a.y;
        As[acol + 2][arow] = a.z;
        As[acol + 3][arow] = a.w;
        *(float4*)&Bs[brow][bcol] = bb;
        __syncthreads();
#pragma unroll
        for (int kk = 0; kk < 8; kk++) {
            float ar[8], br[8];
            *(float4*)(ar)     = *(const float4*)&As[kk][tm];
            *(float4*)(ar + 4) = *(const float4*)&As[kk][tm + 4];
            *(float4*)(br)     = *(const float4*)&Bs[kk][tn];
            *(float4*)(br + 4) = *(const float4*)&Bs[kk][tn + 4];
#pragma unroll
            for (int i = 0; i < 8; i++)
#pragma unroll
                for (int j = 0; j < 8; j++)
                    acc[i][j] = fmaf(ar[i], br[j], acc[i][j]);
        }
    }

    // epilogue
    float bv[8];
    if (MODE >= 1) {
#pragma unroll
        for (int j = 0; j < 8; j += 4) {
            float4 t = *(const float4*)(bias + bn + tn + j);
            bv[j] = t.x; bv[j + 1] = t.y; bv[j + 2] = t.z; bv[j + 3] = t.w;
        }
    }
#pragma unroll
    for (int i = 0; i < 8; i++) {
        int row  = bm + tm + i;
        int orow = (MODE == 2) ? map_win_to_spatial(row) : row;
        float*       cp = C + (size_t)orow * N + bn + tn;
        const float* rp = (MODE >= 2) ? (resid + (size_t)orow * N + bn + tn) : (const float*)0;
#pragma unroll
        for (int j = 0; j < 8; j += 4) {
            float4 v;
            v.x = acc[i][j]; v.y = acc[i][j + 1]; v.z = acc[i][j + 2]; v.w = acc[i][j + 3];
            if (MODE >= 1) { v.x += bv[j]; v.y += bv[j + 1]; v.z += bv[j + 2]; v.w += bv[j + 3]; }
            if (MODE >= 2) {
                float4 r = *(const float4*)(rp + j);
                v.x += r.x; v.y += r.y; v.z += r.z; v.w += r.w;
            }
            *(float4*)(cp + j) = v;
        }
    }
}

// ---------------- windowed attention: one block per (window, head) ----------------
__global__ __launch_bounds__(256)
void attn_kernel(const float* __restrict__ qkv, float* __restrict__ out)
{
    const int win  = blockIdx.x;   // 0..1023
    const int head = blockIdx.y;   // 0..11
    const int tid  = threadIdx.x;

    __shared__ float qs[LWIN * 33];
    __shared__ float ks[LWIN * 33];
    __shared__ float vs[LWIN * 33];
    __shared__ float sc[LWIN * 52];
    __shared__ int   rg[LWIN];

    const float scale = 0.17677669529663687f;  // 1/sqrt(32)
    const size_t base = (size_t)win * LWIN * (3 * CDIM) + head * HD;

    for (int idx = tid; idx < LWIN * HD; idx += 256) {
        int p = idx >> 5, d = idx & 31;
        size_t r = base + (size_t)p * (3 * CDIM);
        qs[p * 33 + d] = qkv[r + d] * scale;
        ks[p * 33 + d] = qkv[r + CDIM + d];
        vs[p * 33 + d] = qkv[r + 2 * CDIM + d];
    }
    if (tid < LWIN) {
        int wi = win & 63;
        int h = (wi >> 3) * WS + tid / WS;
        int w = (wi & 7)  * WS + tid % WS;
        int sh = (h < HH - WS) ? 0 : ((h < HH - 3) ? 1 : 2);
        int sw = (w < WW - WS) ? 0 : ((w < WW - 3) ? 1 : 2);
        rg[tid] = sh * 3 + sw;
    }
    __syncthreads();

    // scores = q*scale @ k^T + mask
    for (int idx = tid; idx < LWIN * LWIN; idx += 256) {
        int i = idx / LWIN, j = idx - i * LWIN;
        float s = 0.0f;
#pragma unroll
        for (int d = 0; d < HD; d++)
            s = fmaf(qs[i * 33 + d], ks[j * 33 + d], s);
        if (rg[i] != rg[j]) s -= 100.0f;
        sc[i * 52 + j] = s;
    }
    __syncthreads();

    // softmax rows (one warp per row)
    int wid = tid >> 5, lane = tid & 31;
    for (int i = wid; i < LWIN; i += 8) {
        float v0 = (lane < LWIN)      ? sc[i * 52 + lane]      : -1e30f;
        float v1 = (lane + 32 < LWIN) ? sc[i * 52 + lane + 32] : -1e30f;
        float m = fmaxf(v0, v1);
#pragma unroll
        for (int off = 16; off; off >>= 1) m = fmaxf(m, __shfl_xor_sync(0xffffffffu, m, off));
        float e0 = (lane < LWIN)      ? expf(v0 - m) : 0.0f;
        float e1 = (lane + 32 < LWIN) ? expf(v1 - m) : 0.0f;
        float s = e0 + e1;
#pragma unroll
        for (int off = 16; off; off >>= 1) s += __shfl_xor_sync(0xffffffffu, s, off);
        float r = 1.0f / s;
        if (lane < LWIN)      sc[i * 52 + lane]      = e0 * r;
        if (lane + 32 < LWIN) sc[i * 52 + lane + 32] = e1 * r;
    }
    __syncthreads();

    // out = softmax @ v  -> (window-order rows, col head*32+d)
    for (int idx = tid; idx < LWIN * HD; idx += 256) {
        int i = idx >> 5, d = idx & 31;
        float s = 0.0f;
#pragma unroll
        for (int j = 0; j < LWIN; j++)
            s = fmaf(sc[i * 52 + j], vs[j * 33 + d], s);
        out[(size_t)(win * LWIN + i) * CDIM + head * HD + d] = s;
    }
}

// ---------------- depthwise 3x3 conv (NHWC) + bias + exact GELU ----------------
__global__ __launch_bounds__(256)
void dwconv_gelu(const float* __restrict__ x, const float* __restrict__ kern,
                 const float* __restrict__ bias, float* __restrict__ out)
{
    int ch = blockIdx.x * 256 + threadIdx.x;   // 0..1535
    int hw = blockIdx.y;                       // 0..3135
    int b  = blockIdx.z;                       // 0..15
    int h = hw / WW, w = hw - h * WW;

    const float* kp = kern + ch * 9;
    float acc = bias[ch];
    size_t brow = (size_t)b * NTOK;
#pragma unroll
    for (int dh = -1; dh <= 1; dh++) {
        int ih = h + dh;
        if ((unsigned)ih >= HH) continue;
#pragma unroll
        for (int dw = -1; dw <= 1; dw++) {
            int iw = w + dw;
            if ((unsigned)iw >= WW) continue;
            acc = fmaf(x[(brow + ih * WW + iw) * HID + ch], kp[(dh + 1) * 3 + (dw + 1)], acc);
        }
    }
    // exact GELU
    float g = 0.5f * acc * (1.0f + erff(acc * 0.70710678118654752f));
    out[(brow + hw) * HID + ch] = g;
}

// ---------------- launcher ----------------
extern "C" void kernel_launch(void* const* d_in, const int* in_sizes, int n_in,
                              void* d_out, int out_size)
{
    const float* x     = (const float*)d_in[0];
    const float* ln1g  = (const float*)d_in[1];
    const float* ln1b  = (const float*)d_in[2];
    const float* qkvw  = (const float*)d_in[3];
    const float* projw = (const float*)d_in[4];
    const float* projb = (const float*)d_in[5];
    const float* ln2g  = (const float*)d_in[6];
    const float* ln2b  = (const float*)d_in[7];
    const float* fc1w  = (const float*)d_in[8];
    const float* fc1b  = (const float*)d_in[9];
    const float* dwk   = (const float*)d_in[10];
    const float* dwb   = (const float*)d_in[11];
    const float* fc2w  = (const float*)d_in[12];
    const float* fc2b  = (const float*)d_in[13];
    float* out = (float*)d_out;

    float *xw, *qkv, *attn, *x2, *xn2, *h1, *h2;
    cudaGetSymbolAddress((void**)&xw,   g_xw);
    cudaGetSymbolAddress((void**)&qkv,  g_qkv);
    cudaGetSymbolAddress((void**)&attn, g_attn);
    cudaGetSymbolAddress((void**)&x2,   g_x2);
    cudaGetSymbolAddress((void**)&xn2,  g_xn2);
    cudaGetSymbolAddress((void**)&h1,   g_h1);
    cudaGetSymbolAddress((void**)&h2,   g_h2);

    // 1. LN1 + roll(-3,-3) + window partition
    ln_kernel<true><<<MTOT, 128>>>(x, ln1g, ln1b, xw);
    // 2. QKV GEMM (no bias)
    sgemm128<0><<<dim3(9, 392), 256>>>(xw, qkvw, qkv, (const float*)0, (const float*)0, CDIM, 3 * CDIM);
    // 3. windowed attention with analytic shift mask
    attn_kernel<<<dim3(1024, HEADS), 256>>>(qkv, attn);
    // 4. proj GEMM + bias + window-reverse scatter + residual(x) -> x2
    sgemm128<2><<<dim3(3, 392), 256>>>(attn, projw, x2, projb, x, CDIM, CDIM);
    // 5. LN2
    ln_kernel<false><<<MTOT, 128>>>(x2, ln2g, ln2b, xn2);
    // 6. fc1 GEMM + bias
    sgemm128<1><<<dim3(12, 392), 256>>>(xn2, fc1w, h1, fc1b, (const float*)0, CDIM, HID);
    // 7. depthwise conv + bias + exact GELU
    dwconv_gelu<<<dim3(6, NTOK, BATCH), 256>>>(h1, dwk, dwb, h2);
    // 8. fc2 GEMM + bias + residual(x2) -> out
    sgemm128<3><<<dim3(3, 392), 256>>>(h2, fc2w, out, fc2b, x2, HID, CDIM);
}

// round 3
// speedup vs baseline: 2.9024x; 2.9024x over previous
#include <cuda_runtime.h>
#include <cuda_fp16.h>
#include <math.h>
#include <stdint.h>

// ---------------- problem constants ----------------
#define BATCH 16
#define HH 56
#define WW 56
#define NTOK 3136            // 56*56
#define CDIM 384
#define HEADS 12
#define HD 32
#define WS 7
#define LWIN 49
#define HID 1536
#define MTOT 50176           // BATCH*NTOK = 392*128

// ---------------- scratch (static device memory; no allocations) ----------------
__device__ __align__(256) __half g_xw   [(size_t)MTOT * CDIM];       // LN1 + window partition
__device__ __align__(256) __half g_qkv  [(size_t)MTOT * 3 * CDIM];
__device__ __align__(256) __half g_attn [(size_t)MTOT * CDIM];       // attn out, window order
__device__ __align__(256) float  g_x2   [(size_t)MTOT * CDIM];       // fp32 residual spine
__device__ __align__(256) __half g_xn2  [(size_t)MTOT * CDIM];
__device__ __align__(256) __half g_h1   [(size_t)MTOT * HID];
__device__ __align__(256) __half g_h2   [(size_t)MTOT * HID];
// fp16 transposed weights: Wt[n][k] = W[k][n]
__device__ __align__(256) __half g_wqkv [(size_t)3 * CDIM * CDIM];
__device__ __align__(256) __half g_wproj[(size_t)CDIM * CDIM];
__device__ __align__(256) __half g_wfc1 [(size_t)HID * CDIM];
__device__ __align__(256) __half g_wfc2 [(size_t)CDIM * HID];

// ---------------- helpers ----------------
__device__ __forceinline__ uint32_t smem_u32(const void* p)
{
    uint32_t a;
    asm("{ .reg .u64 t; cvta.to.shared.u64 t, %1; cvt.u32.u64 %0, t; }" : "=r"(a) : "l"(p));
    return a;
}

#define CP_ASYNC16(dst, src) \
    asm volatile("cp.async.cg.shared.global [%0], [%1], 16;" :: "r"(dst), "l"(src))
#define CP_COMMIT() asm volatile("cp.async.commit_group;" ::: "memory")
#define CP_WAIT1()  asm volatile("cp.async.wait_group 1;" ::: "memory")

#define LDSM_X4(r0, r1, r2, r3, addr) \
    asm volatile("ldmatrix.sync.aligned.m8n8.x4.shared.b16 {%0,%1,%2,%3}, [%4];" \
                 : "=r"(r0), "=r"(r1), "=r"(r2), "=r"(r3) : "r"(addr))

#define MMA16816(c, a, b) \
    asm volatile("mma.sync.aligned.m16n8k16.row.col.f32.f16.f16.f32 " \
                 "{%0,%1,%2,%3}, {%4,%5,%6,%7}, {%8,%9}, {%0,%1,%2,%3};" \
                 : "+f"((c)[0]), "+f"((c)[1]), "+f"((c)[2]), "+f"((c)[3]) \
                 : "r"((a)[0]), "r"((a)[1]), "r"((a)[2]), "r"((a)[3]), \
                   "r"((b)[0]), "r"((b)[1]))

// window-order row -> spatial row (window reverse, NO un-shift, per reference)
__device__ __forceinline__ int map_win_to_spatial(int row)
{
    int b  = row / NTOK;
    int t  = row - b * NTOK;
    int wi = t / LWIN;
    int p  = t - wi * LWIN;
    int pr = p / WS;
    int pc = p - pr * WS;
    int h  = (wi >> 3) * WS + pr;
    int w  = (wi & 7)  * WS + pc;
    return b * NTOK + h * WW + w;
}

// ---------------- weight prep: fp32 [K,N] -> fp16 [N,K] (transpose) ----------------
__global__ __launch_bounds__(256)
void wprep(const float* __restrict__ W, __half* __restrict__ Wt, int K, int N)
{
    __shared__ float t[32][33];
    int k0 = blockIdx.y * 32, n0 = blockIdx.x * 32;
    int tx = threadIdx.x, ty = threadIdx.y;   // 32 x 8
#pragma unroll
    for (int i = 0; i < 32; i += 8)
        t[ty + i][tx] = W[(size_t)(k0 + ty + i) * N + n0 + tx];
    __syncthreads();
#pragma unroll
    for (int i = 0; i < 32; i += 8)
        Wt[(size_t)(n0 + ty + i) * K + k0 + tx] = __float2half(t[tx][ty + i]);
}

// ---------------- LayerNorm (optionally fused with shift + window partition) ----------------
template <bool SHIFT>
__global__ __launch_bounds__(128)
void ln_kernel(const float* __restrict__ x, const float* __restrict__ g,
               const float* __restrict__ b, __half* __restrict__ out)
{
    int row = blockIdx.x;
    int srow;
    if (SHIFT) {
        int bb = row / NTOK;
        int t  = row - bb * NTOK;
        int wi = t / LWIN;
        int p  = t - wi * LWIN;
        int pr = p / WS;
        int pc = p - pr * WS;
        int h  = (wi >> 3) * WS + pr + 3; if (h >= HH) h -= HH;
        int w  = (wi & 7)  * WS + pc + 3; if (w >= WW) w -= WW;
        srow = bb * NTOK + h * WW + w;
    } else {
        srow = row;
    }
    const float* xr = x + (size_t)srow * CDIM;
    int tid = threadIdx.x;
    float v0 = xr[tid], v1 = xr[tid + 128], v2 = xr[tid + 256];
    float s  = v0 + v1 + v2;
    float ss = v0 * v0 + v1 * v1 + v2 * v2;
#pragma unroll
    for (int off = 16; off; off >>= 1) {
        s  += __shfl_xor_sync(0xffffffffu, s,  off);
        ss += __shfl_xor_sync(0xffffffffu, ss, off);
    }
    __shared__ float rs[4], rq[4];
    __shared__ float mean_s, inv_s;
    if ((tid & 31) == 0) { rs[tid >> 5] = s; rq[tid >> 5] = ss; }
    __syncthreads();
    if (tid == 0) {
        float S = rs[0] + rs[1] + rs[2] + rs[3];
        float Q = rq[0] + rq[1] + rq[2] + rq[3];
        float m = S * (1.0f / CDIM);
        float var = Q * (1.0f / CDIM) - m * m;
        mean_s = m;
        inv_s  = rsqrtf(var + 1e-5f);
    }
    __syncthreads();
    float m = mean_s, inv = inv_s;
    __half* o = out + (size_t)row * CDIM;
    o[tid]       = __float2half((v0 - m) * inv * g[tid]       + b[tid]);
    o[tid + 128] = __float2half((v1 - m) * inv * g[tid + 128] + b[tid + 128]);
    o[tid + 256] = __float2half((v2 - m) * inv * g[tid + 256] + b[tid + 256]);
}

// ---------------- fp16 HMMA GEMM: C(MxN) = A(MxK) * Bw(NxK)^T, fp32 accumulate -------------
// MODE 0: C fp16, no bias    MODE 1: C fp16 + bias
// MODE 2: C fp32 + bias + win->spatial scatter + residual
// MODE 3: C fp32 + bias + residual (same row)
#define BMM 128
#define BNN 128
#define BKK 32
#define STG 3
#define STG_BYTES 8192                 // 128 rows * 64 B
#define GEMM_SMEM (STG * 2 * STG_BYTES)   // 49152

template <int MODE>
__global__ __launch_bounds__(256)
void hgemm(const __half* __restrict__ A, const __half* __restrict__ Bw,
           void* __restrict__ Cout, const float* __restrict__ bias,
           const float* __restrict__ resid, int K, int N)
{
    extern __shared__ char smem[];
    const uint32_t sA = smem_u32(smem);
    const uint32_t sB = sA + STG * STG_BYTES;

    const int tid  = threadIdx.x;
    const int wid  = tid >> 5;
    const int lane = tid & 31;
    const int bm   = blockIdx.y * BMM;
    const int bn   = blockIdx.x * BNN;
    const int wm0  = (wid & 3) * 32;   // warp row offset in tile
    const int wn0  = (wid >> 2) * 64;  // warp col offset in tile

    // global load mapping: 512 16B-chunks per tile, 2 per thread
    const int r0 = tid >> 1;                 // rows tid/2 and tid/2+... chunk0 = tid, chunk1 = tid+256
    // chunk id ch: row = ch>>2, c16 = ch&3
    const int lrow0 = tid >> 2,          lc0 = tid & 3;
    const int lrow1 = (tid + 256) >> 2,  lc1 = tid & 3;   // (tid+256)&3 == tid&3
    (void)r0;
    const uint32_t so0 = (uint32_t)lrow0 * 64 + (uint32_t)((lc0 ^ (lrow0 & 3)) << 4);
    const uint32_t so1 = (uint32_t)lrow1 * 64 + (uint32_t)((lc1 ^ (lrow1 & 3)) << 4);

    const int NC = K / BKK;

    // prologue: stages 0,1
#pragma unroll
    for (int c = 0; c < 2; c++) {
        const __half* Ag = A  + (size_t)bm * K + c * BKK;
        const __half* Bg = Bw + (size_t)bn * K + c * BKK;
        uint32_t da = sA + c * STG_BYTES;
        uint32_t db = sB + c * STG_BYTES;
        CP_ASYNC16(da + so0, Ag + (size_t)lrow0 * K + lc0 * 8);
        CP_ASYNC16(da + so1, Ag + (size_t)lrow1 * K + lc1 * 8);
        CP_ASYNC16(db + so0, Bg + (size_t)lrow0 * K + lc0 * 8);
        CP_ASYNC16(db + so1, Bg + (size_t)lrow1 * K + lc1 * 8);
        CP_COMMIT();
    }

    float acc[2][8][4];
#pragma unroll
    for (int i = 0; i < 2; i++)
#pragma unroll
        for (int j = 0; j < 8; j++)
#pragma unroll
            for (int r = 0; r < 4; r++) acc[i][j][r] = 0.0f;

    // per-lane ldmatrix row/chunk components
    const int a_row_l = ((lane & 8)) + (lane & 7);        // + fi*16
    const int a_chk_l = (lane >> 4) & 1;                  // + 2*ks
    const int b_row_l = (((lane >> 4) & 1) << 3) + (lane & 7);  // + nj*16
    const int b_chk_l = (lane >> 3) & 1;                  // + 2*ks

    for (int c = 0; c < NC; c++) {
        const int st = c % STG;
        CP_WAIT1();
        __syncthreads();

        if (c + 2 < NC) {
            const int cc = c + 2, s2 = cc % STG;
            const __half* Ag = A  + (size_t)bm * K + cc * BKK;
            const __half* Bg = Bw + (size_t)bn * K + cc * BKK;
            uint32_t da = sA + s2 * STG_BYTES;
            uint32_t db = sB + s2 * STG_BYTES;
            CP_ASYNC16(da + so0, Ag + (size_t)lrow0 * K + lc0 * 8);
            CP_ASYNC16(da + so1, Ag + (size_t)lrow1 * K + lc1 * 8);
            CP_ASYNC16(db + so0, Bg + (size_t)lrow0 * K + lc0 * 8);
            CP_ASYNC16(db + so1, Bg + (size_t)lrow1 * K + lc1 * 8);
        }
        CP_COMMIT();

        const uint32_t ab = sA + st * STG_BYTES;
        const uint32_t bb = sB + st * STG_BYTES;
#pragma unroll
        for (int ks = 0; ks < 2; ks++) {
            uint32_t a[2][4], b[8][2];
#pragma unroll
            for (int fi = 0; fi < 2; fi++) {
                int row = wm0 + fi * 16 + a_row_l;
                int chk = 2 * ks + a_chk_l;
                uint32_t ad = ab + (uint32_t)row * 64 + (uint32_t)((chk ^ (row & 3)) << 4);
                LDSM_X4(a[fi][0], a[fi][1], a[fi][2], a[fi][3], ad);
            }
#pragma unroll
            for (int nj = 0; nj < 4; nj++) {
                int row = wn0 + nj * 16 + b_row_l;
                int chk = 2 * ks + b_chk_l;
                uint32_t bd = bb + (uint32_t)row * 64 + (uint32_t)((chk ^ (row & 3)) << 4);
                LDSM_X4(b[nj * 2][0], b[nj * 2][1], b[nj * 2 + 1][0], b[nj * 2 + 1][1], bd);
            }
#pragma unroll
            for (int fi = 0; fi < 2; fi++)
#pragma unroll
                for (int j = 0; j < 8; j++)
                    MMA16816(acc[fi][j], a[fi], b[j]);
        }
        __syncthreads();
    }

    // ---------------- epilogue ----------------
#pragma unroll
    for (int fi = 0; fi < 2; fi++) {
#pragma unroll
        for (int h = 0; h < 2; h++) {
            int row  = bm + wm0 + fi * 16 + (lane >> 2) + h * 8;
            int orow = (MODE == 2) ? map_win_to_spatial(row) : row;
#pragma unroll
            for (int j = 0; j < 8; j++) {
                int col = bn + wn0 + j * 8 + (lane & 3) * 2;
                float v0 = acc[fi][j][h * 2];
                float v1 = acc[fi][j][h * 2 + 1];
                if (MODE >= 1) { v0 += bias[col]; v1 += bias[col + 1]; }
                if (MODE >= 2) {
                    const float* rp = resid + (size_t)orow * N + col;
                    float2 rr = *(const float2*)rp;
                    float2 o; o.x = v0 + rr.x; o.y = v1 + rr.y;
                    *(float2*)((float*)Cout + (size_t)orow * N + col) = o;
                } else {
                    *(__half2*)((__half*)Cout + (size_t)row * N + col) =
                        __floats2half2_rn(v0, v1);
                }
            }
        }
    }
}

// ---------------- windowed attention: one block per (window, head), fp16 I/O ----------------
__global__ __launch_bounds__(256)
void attn_kernel(const __half* __restrict__ qkv, __half* __restrict__ out)
{
    const int win  = blockIdx.x;
    const int head = blockIdx.y;
    const int tid  = threadIdx.x;

    __shared__ float qs[LWIN * 33];
    __shared__ float ks[LWIN * 33];
    __shared__ float vs[LWIN * 33];
    __shared__ float sc[LWIN * 52];
    __shared__ int   rg[LWIN];

    const float scale = 0.17677669529663687f;
    const size_t base = (size_t)win * LWIN * (3 * CDIM) + head * HD;

    for (int idx = tid; idx < LWIN * HD; idx += 256) {
        int p = idx >> 5, d = idx & 31;
        size_t r = base + (size_t)p * (3 * CDIM);
        qs[p * 33 + d] = __half2float(qkv[r + d]) * scale;
        ks[p * 33 + d] = __half2float(qkv[r + CDIM + d]);
        vs[p * 33 + d] = __half2float(qkv[r + 2 * CDIM + d]);
    }
    if (tid < LWIN) {
        int wi = win & 63;
        int h = (wi >> 3) * WS + tid / WS;
        int w = (wi & 7)  * WS + tid % WS;
        int sh = (h < HH - WS) ? 0 : ((h < HH - 3) ? 1 : 2);
        int sw = (w < WW - WS) ? 0 : ((w < WW - 3) ? 1 : 2);
        rg[tid] = sh * 3 + sw;
    }
    __syncthreads();

    for (int idx = tid; idx < LWIN * LWIN; idx += 256) {
        int i = idx / LWIN, j = idx - i * LWIN;
        float s = 0.0f;
#pragma unroll
        for (int d = 0; d < HD; d++)
            s = fmaf(qs[i * 33 + d], ks[j * 33 + d], s);
        if (rg[i] != rg[j]) s -= 100.0f;
        sc[i * 52 + j] = s;
    }
    __syncthreads();

    int wid = tid >> 5, lane = tid & 31;
    for (int i = wid; i < LWIN; i += 8) {
        float v0 = (lane < LWIN)      ? sc[i * 52 + lane]      : -1e30f;
        float v1 = (lane + 32 < LWIN) ? sc[i * 52 + lane + 32] : -1e30f;
        float m = fmaxf(v0, v1);
#pragma unroll
        for (int off = 16; off; off >>= 1) m = fmaxf(m, __shfl_xor_sync(0xffffffffu, m, off));
        float e0 = (lane < LWIN)      ? expf(v0 - m) : 0.0f;
        float e1 = (lane + 32 < LWIN) ? expf(v1 - m) : 0.0f;
        float s = e0 + e1;
#pragma unroll
        for (int off = 16; off; off >>= 1) s += __shfl_xor_sync(0xffffffffu, s, off);
        float r = 1.0f / s;
        if (lane < LWIN)      sc[i * 52 + lane]      = e0 * r;
        if (lane + 32 < LWIN) sc[i * 52 + lane + 32] = e1 * r;
    }
    __syncthreads();

    for (int idx = tid; idx < LWIN * HD; idx += 256) {
        int i = idx >> 5, d = idx & 31;
        float s = 0.0f;
#pragma unroll
        for (int j = 0; j < LWIN; j++)
            s = fmaf(sc[i * 52 + j], vs[j * 33 + d], s);
        out[(size_t)(win * LWIN + i) * CDIM + head * HD + d] = __float2half(s);
    }
}

// ---------------- depthwise 3x3 conv (NHWC) + bias + exact GELU, fp16 I/O ----------------
__global__ __launch_bounds__(256)
void dwconv_gelu(const __half* __restrict__ x, const float* __restrict__ kern,
                 const float* __restrict__ bias, __half* __restrict__ out)
{
    int ch = blockIdx.x * 256 + threadIdx.x;
    int hw = blockIdx.y;
    int b  = blockIdx.z;
    int h = hw / WW, w = hw - h * WW;

    const float* kp = kern + ch * 9;
    float acc = bias[ch];
    size_t brow = (size_t)b * NTOK;
#pragma unroll
    for (int dh = -1; dh <= 1; dh++) {
        int ih = h + dh;
        if ((unsigned)ih >= HH) continue;
#pragma unroll
        for (int dw = -1; dw <= 1; dw++) {
            int iw = w + dw;
            if ((unsigned)iw >= WW) continue;
            acc = fmaf(__half2float(x[(brow + ih * WW + iw) * HID + ch]),
                       kp[(dh + 1) * 3 + (dw + 1)], acc);
        }
    }
    float g = 0.5f * acc * (1.0f + erff(acc * 0.70710678118654752f));
    out[(brow + hw) * HID + ch] = __float2half(g);
}

// ---------------- launcher ----------------
extern "C" void kernel_launch(void* const* d_in, const int* in_sizes, int n_in,
                              void* d_out, int out_size)
{
    const float* x     = (const float*)d_in[0];
    const float* ln1g  = (const float*)d_in[1];
    const float* ln1b  = (const float*)d_in[2];
    const float* qkvw  = (const float*)d_in[3];
    const float* projw = (const float*)d_in[4];
    const float* projb = (const float*)d_in[5];
    const float* ln2g  = (const float*)d_in[6];
    const float* ln2b  = (const float*)d_in[7];
    const float* fc1w  = (const float*)d_in[8];
    const float* fc1b  = (const float*)d_in[9];
    const float* dwk   = (const float*)d_in[10];
    const float* dwb   = (const float*)d_in[11];
    const float* fc2w  = (const float*)d_in[12];
    const float* fc2b  = (const float*)d_in[13];
    float* out = (float*)d_out;

    __half *xw, *qkv, *attn, *xn2, *h1, *h2, *wqkv, *wproj, *wfc1, *wfc2;
    float  *x2;
    cudaGetSymbolAddress((void**)&xw,    g_xw);
    cudaGetSymbolAddress((void**)&qkv,   g_qkv);
    cudaGetSymbolAddress((void**)&attn,  g_attn);
    cudaGetSymbolAddress((void**)&x2,    g_x2);
    cudaGetSymbolAddress((void**)&xn2,   g_xn2);
    cudaGetSymbolAddress((void**)&h1,    g_h1);
    cudaGetSymbolAddress((void**)&h2,    g_h2);
    cudaGetSymbolAddress((void**)&wqkv,  g_wqkv);
    cudaGetSymbolAddress((void**)&wproj, g_wproj);
    cudaGetSymbolAddress((void**)&wfc1,  g_wfc1);
    cudaGetSymbolAddress((void**)&wfc2,  g_wfc2);

    cudaFuncSetAttribute(hgemm<0>, cudaFuncAttributeMaxDynamicSharedMemorySize, GEMM_SMEM);
    cudaFuncSetAttribute(hgemm<1>, cudaFuncAttributeMaxDynamicSharedMemorySize, GEMM_SMEM);
    cudaFuncSetAttribute(hgemm<2>, cudaFuncAttributeMaxDynamicSharedMemorySize, GEMM_SMEM);
    cudaFuncSetAttribute(hgemm<3>, cudaFuncAttributeMaxDynamicSharedMemorySize, GEMM_SMEM);

    // weight prep: fp32 [K,N] -> fp16 [N,K]
    wprep<<<dim3(1152 / 32, 384 / 32),  dim3(32, 8)>>>(qkvw,  wqkv,  384, 1152);
    wprep<<<dim3(384 / 32,  384 / 32),  dim3(32, 8)>>>(projw, wproj, 384, 384);
    wprep<<<dim3(1536 / 32, 384 / 32),  dim3(32, 8)>>>(fc1w,  wfc1,  384, 1536);
    wprep<<<dim3(384 / 32,  1536 / 32), dim3(32, 8)>>>(fc2w,  wfc2,  1536, 384);

    // 1. LN1 + roll(-3,-3) + window partition (fp16 out)
    ln_kernel<true><<<MTOT, 128>>>(x, ln1g, ln1b, xw);
    // 2. QKV GEMM
    hgemm<0><<<dim3(9, 392), 256, GEMM_SMEM>>>(xw, wqkv, qkv, (const float*)0, (const float*)0, CDIM, 3 * CDIM);
    // 3. windowed attention with analytic shift mask
    attn_kernel<<<dim3(1024, HEADS), 256>>>(qkv, attn);
    // 4. proj GEMM + bias + window-reverse scatter + residual(x) -> x2 (fp32)
    hgemm<2><<<dim3(3, 392), 256, GEMM_SMEM>>>(attn, wproj, x2, projb, x, CDIM, CDIM);
    // 5. LN2 (fp16 out)
    ln_kernel<false><<<MTOT, 128>>>(x2, ln2g, ln2b, xn2);
    // 6. fc1 GEMM + bias
    hgemm<1><<<dim3(12, 392), 256, GEMM_SMEM>>>(xn2, wfc1, h1, fc1b, (const float*)0, CDIM, HID);
    // 7. depthwise conv + bias + exact GELU
    dwconv_gelu<<<dim3(6, NTOK, BATCH), 256>>>(h1, dwk, dwb, h2);
    // 8. fc2 GEMM + bias + residual(x2) -> out (fp32)
    hgemm<3><<<dim3(3, 392), 256, GEMM_SMEM>>>(h2, wfc2, out, fc2b, x2, HID, CDIM);
}

// round 4
// speedup vs baseline: 3.5682x; 1.2294x over previous
#include <cuda_runtime.h>
#include <cuda_fp16.h>
#include <math.h>
#include <stdint.h>

// ---------------- problem constants ----------------
#define BATCH 16
#define HH 56
#define WW 56
#define NTOK 3136            // 56*56
#define CDIM 384
#define HEADS 12
#define HD 32
#define WS 7
#define LWIN 49
#define HID 1536
#define MTOT 50176           // BATCH*NTOK = 392*128

// ---------------- scratch (static device memory; no allocations) ----------------
__device__ __align__(256) __half g_xw   [(size_t)MTOT * CDIM];       // LN1 + window partition
__device__ __align__(256) __half g_qkv  [(size_t)MTOT * 3 * CDIM];
__device__ __align__(256) __half g_attn [(size_t)MTOT * CDIM];       // attn out, window order
__device__ __align__(256) float  g_x2   [(size_t)MTOT * CDIM];       // fp32 residual spine
__device__ __align__(256) __half g_xn2  [(size_t)MTOT * CDIM];
__device__ __align__(256) __half g_h1   [(size_t)MTOT * HID];
__device__ __align__(256) __half g_h2   [(size_t)MTOT * HID];
// fp16 transposed weights: Wt[n][k] = W[k][n]
__device__ __align__(256) __half g_wqkv [(size_t)3 * CDIM * CDIM];
__device__ __align__(256) __half g_wproj[(size_t)CDIM * CDIM];
__device__ __align__(256) __half g_wfc1 [(size_t)HID * CDIM];
__device__ __align__(256) __half g_wfc2 [(size_t)CDIM * HID];

// ---------------- helpers ----------------
__device__ __forceinline__ uint32_t smem_u32(const void* p)
{
    uint32_t a;
    asm("{ .reg .u64 t; cvta.to.shared.u64 t, %1; cvt.u32.u64 %0, t; }" : "=r"(a) : "l"(p));
    return a;
}

#define CP_ASYNC16(dst, src) \
    asm volatile("cp.async.cg.shared.global [%0], [%1], 16;" :: "r"(dst), "l"(src))
#define CP_COMMIT() asm volatile("cp.async.commit_group;" ::: "memory")
#define CP_WAIT1()  asm volatile("cp.async.wait_group 1;" ::: "memory")

#define LDSM_X4(r0, r1, r2, r3, addr) \
    asm volatile("ldmatrix.sync.aligned.m8n8.x4.shared.b16 {%0,%1,%2,%3}, [%4];" \
                 : "=r"(r0), "=r"(r1), "=r"(r2), "=r"(r3) : "r"(addr))

#define MMA16816(c, a, b) \
    asm volatile("mma.sync.aligned.m16n8k16.row.col.f32.f16.f16.f32 " \
                 "{%0,%1,%2,%3}, {%4,%5,%6,%7}, {%8,%9}, {%0,%1,%2,%3};" \
                 : "+f"((c)[0]), "+f"((c)[1]), "+f"((c)[2]), "+f"((c)[3]) \
                 : "r"((a)[0]), "r"((a)[1]), "r"((a)[2]), "r"((a)[3]), \
                   "r"((b)[0]), "r"((b)[1]))

// window-order row -> spatial row (window reverse, NO un-shift, per reference)
__device__ __forceinline__ int map_win_to_spatial(int row)
{
    int b  = row / NTOK;
    int t  = row - b * NTOK;
    int wi = t / LWIN;
    int p  = t - wi * LWIN;
    int pr = p / WS;
    int pc = p - pr * WS;
    int h  = (wi >> 3) * WS + pr;
    int w  = (wi & 7)  * WS + pc;
    return b * NTOK + h * WW + w;
}

// ---------------- weight prep: fp32 [K,N] -> fp16 [N,K] (transpose) ----------------
__global__ __launch_bounds__(256)
void wprep(const float* __restrict__ W, __half* __restrict__ Wt, int K, int N)
{
    __shared__ float t[32][33];
    int k0 = blockIdx.y * 32, n0 = blockIdx.x * 32;
    int tx = threadIdx.x, ty = threadIdx.y;   // 32 x 8
#pragma unroll
    for (int i = 0; i < 32; i += 8)
        t[ty + i][tx] = W[(size_t)(k0 + ty + i) * N + n0 + tx];
    __syncthreads();
#pragma unroll
    for (int i = 0; i < 32; i += 8)
        Wt[(size_t)(n0 + ty + i) * K + k0 + tx] = __float2half(t[tx][ty + i]);
}

// ---------------- LayerNorm (optionally fused with shift + window partition) ----------------
template <bool SHIFT>
__global__ __launch_bounds__(128)
void ln_kernel(const float* __restrict__ x, const float* __restrict__ g,
               const float* __restrict__ b, __half* __restrict__ out)
{
    int row = blockIdx.x;
    int srow;
    if (SHIFT) {
        int bb = row / NTOK;
        int t  = row - bb * NTOK;
        int wi = t / LWIN;
        int p  = t - wi * LWIN;
        int pr = p / WS;
        int pc = p - pr * WS;
        int h  = (wi >> 3) * WS + pr + 3; if (h >= HH) h -= HH;
        int w  = (wi & 7)  * WS + pc + 3; if (w >= WW) w -= WW;
        srow = bb * NTOK + h * WW + w;
    } else {
        srow = row;
    }
    const float* xr = x + (size_t)srow * CDIM;
    int tid = threadIdx.x;
    float v0 = xr[tid], v1 = xr[tid + 128], v2 = xr[tid + 256];
    float s  = v0 + v1 + v2;
    float ss = v0 * v0 + v1 * v1 + v2 * v2;
#pragma unroll
    for (int off = 16; off; off >>= 1) {
        s  += __shfl_xor_sync(0xffffffffu, s,  off);
        ss += __shfl_xor_sync(0xffffffffu, ss, off);
    }
    __shared__ float rs[4], rq[4];
    __shared__ float mean_s, inv_s;
    if ((tid & 31) == 0) { rs[tid >> 5] = s; rq[tid >> 5] = ss; }
    __syncthreads();
    if (tid == 0) {
        float S = rs[0] + rs[1] + rs[2] + rs[3];
        float Q = rq[0] + rq[1] + rq[2] + rq[3];
        float m = S * (1.0f / CDIM);
        float var = Q * (1.0f / CDIM) - m * m;
        mean_s = m;
        inv_s  = rsqrtf(var + 1e-5f);
    }
    __syncthreads();
    float m = mean_s, inv = inv_s;
    __half* o = out + (size_t)row * CDIM;
    o[tid]       = __float2half((v0 - m) * inv * g[tid]       + b[tid]);
    o[tid + 128] = __float2half((v1 - m) * inv * g[tid + 128] + b[tid + 128]);
    o[tid + 256] = __float2half((v2 - m) * inv * g[tid + 256] + b[tid + 256]);
}

// ---------------- fp16 HMMA GEMM: C(MxN) = A(MxK) * Bw(NxK)^T, fp32 accumulate -------------
// Tile 128x128x64, 3-stage cp.async pipeline, 2 CTAs/SM.
// MODE 0: C fp16, no bias    MODE 1: C fp16 + bias
// MODE 2: C fp32 + bias + win->spatial scatter + residual
// MODE 3: C fp32 + bias + residual (same row)
#define BMM 128
#define BNN 128
#define BKK 64
#define STG 3
#define STG_BYTES 16384                   // 128 rows * 128 B
#define GEMM_SMEM (STG * 2 * STG_BYTES)   // 98304

template <int MODE>
__global__ __launch_bounds__(256, 2)
void hgemm(const __half* __restrict__ A, const __half* __restrict__ Bw,
           void* __restrict__ Cout, const float* __restrict__ bias,
           const float* __restrict__ resid, int K, int N)
{
    extern __shared__ char smem[];
    const uint32_t sA = smem_u32(smem);
    const uint32_t sB = sA + STG * STG_BYTES;

    const int tid  = threadIdx.x;
    const int wid  = tid >> 5;
    const int lane = tid & 31;
    const int bm   = blockIdx.y * BMM;
    const int bn   = blockIdx.x * BNN;
    const int wm0  = (wid & 3) * 32;   // warp row offset in tile
    const int wn0  = (wid >> 2) * 64;  // warp col offset in tile

    // global load mapping: 1024 16B-chunks per tile (A or B), 4 per thread each
    // chunk idx = tid + q*256: row = idx>>3, c16 = idx&7 (== tid&7)
    const int lc = tid & 7;
    int   lrow[4];
    uint32_t so[4];
#pragma unroll
    for (int q = 0; q < 4; q++) {
        lrow[q] = (tid + q * 256) >> 3;
        so[q]   = (uint32_t)lrow[q] * 128 + (uint32_t)((lc ^ (lrow[q] & 7)) << 4);
    }

    const int NC = K / BKK;

    // prologue: stages 0,1
#pragma unroll
    for (int c = 0; c < 2; c++) {
        const __half* Ag = A  + (size_t)bm * K + c * BKK;
        const __half* Bg = Bw + (size_t)bn * K + c * BKK;
        uint32_t da = sA + c * STG_BYTES;
        uint32_t db = sB + c * STG_BYTES;
#pragma unroll
        for (int q = 0; q < 4; q++) {
            CP_ASYNC16(da + so[q], Ag + (size_t)lrow[q] * K + lc * 8);
            CP_ASYNC16(db + so[q], Bg + (size_t)lrow[q] * K + lc * 8);
        }
        CP_COMMIT();
    }

    float acc[2][8][4];
#pragma unroll
    for (int i = 0; i < 2; i++)
#pragma unroll
        for (int j = 0; j < 8; j++)
#pragma unroll
            for (int r = 0; r < 4; r++) acc[i][j][r] = 0.0f;

    // per-lane ldmatrix row/chunk components
    const int a_row_l = (lane & 8) + (lane & 7);                // + fi*16
    const int a_chk_l = (lane >> 4) & 1;                        // + 2*ks
    const int b_row_l = (((lane >> 4) & 1) << 3) + (lane & 7);  // + nj*16
    const int b_chk_l = (lane >> 3) & 1;                        // + 2*ks

    for (int c = 0; c < NC; c++) {
        const int st = c % STG;
        CP_WAIT1();
        __syncthreads();

        if (c + 2 < NC) {
            const int cc = c + 2, s2 = cc % STG;
            const __half* Ag = A  + (size_t)bm * K + cc * BKK;
            const __half* Bg = Bw + (size_t)bn * K + cc * BKK;
            uint32_t da = sA + s2 * STG_BYTES;
            uint32_t db = sB + s2 * STG_BYTES;
#pragma unroll
            for (int q = 0; q < 4; q++) {
                CP_ASYNC16(da + so[q], Ag + (size_t)lrow[q] * K + lc * 8);
                CP_ASYNC16(db + so[q], Bg + (size_t)lrow[q] * K + lc * 8);
            }
        }
        CP_COMMIT();

        const uint32_t ab = sA + st * STG_BYTES;
        const uint32_t bb = sB + st * STG_BYTES;
#pragma unroll
        for (int ks = 0; ks < 4; ks++) {
            uint32_t a[2][4], b[8][2];
#pragma unroll
            for (int fi = 0; fi < 2; fi++) {
                int row = wm0 + fi * 16 + a_row_l;
                int chk = 2 * ks + a_chk_l;
                uint32_t ad = ab + (uint32_t)row * 128 + (uint32_t)((chk ^ (row & 7)) << 4);
                LDSM_X4(a[fi][0], a[fi][1], a[fi][2], a[fi][3], ad);
            }
#pragma unroll
            for (int nj = 0; nj < 4; nj++) {
                int row = wn0 + nj * 16 + b_row_l;
                int chk = 2 * ks + b_chk_l;
                uint32_t bd = bb + (uint32_t)row * 128 + (uint32_t)((chk ^ (row & 7)) << 4);
                LDSM_X4(b[nj * 2][0], b[nj * 2][1], b[nj * 2 + 1][0], b[nj * 2 + 1][1], bd);
            }
#pragma unroll
            for (int fi = 0; fi < 2; fi++)
#pragma unroll
                for (int j = 0; j < 8; j++)
                    MMA16816(acc[fi][j], a[fi], b[j]);
        }
        __syncthreads();
    }

    // ---------------- epilogue ----------------
#pragma unroll
    for (int fi = 0; fi < 2; fi++) {
#pragma unroll
        for (int h = 0; h < 2; h++) {
            int row  = bm + wm0 + fi * 16 + (lane >> 2) + h * 8;
            int orow = (MODE == 2) ? map_win_to_spatial(row) : row;
#pragma unroll
            for (int j = 0; j < 8; j++) {
                int col = bn + wn0 + j * 8 + (lane & 3) * 2;
                float v0 = acc[fi][j][h * 2];
                float v1 = acc[fi][j][h * 2 + 1];
                if (MODE >= 1) { v0 += bias[col]; v1 += bias[col + 1]; }
                if (MODE >= 2) {
                    const float* rp = resid + (size_t)orow * N + col;
                    float2 rr = *(const float2*)rp;
                    float2 o; o.x = v0 + rr.x; o.y = v1 + rr.y;
                    *(float2*)((float*)Cout + (size_t)orow * N + col) = o;
                } else {
                    *(__half2*)((__half*)Cout + (size_t)row * N + col) =
                        __floats2half2_rn(v0, v1);
                }
            }
        }
    }
}

// ---------------- windowed attention: one block per (window, head), half2-resident --------
__global__ __launch_bounds__(256)
void attn_kernel(const __half* __restrict__ qkv, __half* __restrict__ out)
{
    const int win  = blockIdx.x;
    const int head = blockIdx.y;
    const int tid  = threadIdx.x;

    __shared__ __half2 qh[LWIN * 17];
    __shared__ __half2 kh[LWIN * 17];
    __shared__ __half2 vh[LWIN * 17];
    __shared__ float   sc[LWIN * 52];
    __shared__ int     rg[LWIN];

    const float scale = 0.17677669529663687f;  // 1/sqrt(32)
    const size_t base = (size_t)win * LWIN * (3 * CDIM) + head * HD;

    for (int idx = tid; idx < LWIN * 16; idx += 256) {
        int p = idx >> 4, d2 = idx & 15;
        const __half2* r = (const __half2*)(qkv + base + (size_t)p * (3 * CDIM));
        qh[p * 17 + d2] = r[d2];
        kh[p * 17 + d2] = r[CDIM / 2 + d2];
        vh[p * 17 + d2] = r[CDIM + d2];
    }
    if (tid < LWIN) {
        int wi = win & 63;
        int h = (wi >> 3) * WS + tid / WS;
        int w = (wi & 7)  * WS + tid % WS;
        int sh = (h < HH - WS) ? 0 : ((h < HH - 3) ? 1 : 2);
        int sw = (w < WW - WS) ? 0 : ((w < WW - 3) ? 1 : 2);
        rg[tid] = sh * 3 + sw;
    }
    __syncthreads();

    // scores = (q @ k^T) * scale + mask
    for (int idx = tid; idx < LWIN * LWIN; idx += 256) {
        int i = idx / LWIN, j = idx - i * LWIN;
        float s = 0.0f;
#pragma unroll
        for (int d2 = 0; d2 < 16; d2++) {
            float2 a = __half22float2(qh[i * 17 + d2]);
            float2 b = __half22float2(kh[j * 17 + d2]);
            s = fmaf(a.x, b.x, s);
            s = fmaf(a.y, b.y, s);
        }
        s *= scale;
        if (rg[i] != rg[j]) s -= 100.0f;
        sc[i * 52 + j] = s;
    }
    __syncthreads();

    // softmax rows (one warp per row)
    int wid = tid >> 5, lane = tid & 31;
    for (int i = wid; i < LWIN; i += 8) {
        float v0 = (lane < LWIN)      ? sc[i * 52 + lane]      : -1e30f;
        float v1 = (lane + 32 < LWIN) ? sc[i * 52 + lane + 32] : -1e30f;
        float m = fmaxf(v0, v1);
#pragma unroll
        for (int off = 16; off; off >>= 1) m = fmaxf(m, __shfl_xor_sync(0xffffffffu, m, off));
        float e0 = (lane < LWIN)      ? expf(v0 - m) : 0.0f;
        float e1 = (lane + 32 < LWIN) ? expf(v1 - m) : 0.0f;
        float s = e0 + e1;
#pragma unroll
        for (int off = 16; off; off >>= 1) s += __shfl_xor_sync(0xffffffffu, s, off);
        float r = 1.0f / s;
        if (lane < LWIN)      sc[i * 52 + lane]      = e0 * r;
        if (lane + 32 < LWIN) sc[i * 52 + lane + 32] = e1 * r;
    }
    __syncthreads();

    // out = softmax @ v
    for (int idx = tid; idx < LWIN * 16; idx += 256) {
        int i = idx >> 4, d2 = idx & 15;
        float ox = 0.0f, oy = 0.0f;
#pragma unroll 7
        for (int j = 0; j < LWIN; j++) {
            float p = sc[i * 52 + j];
            float2 v = __half22float2(vh[j * 17 + d2]);
            ox = fmaf(p, v.x, ox);
            oy = fmaf(p, v.y, oy);
        }
        *(__half2*)(out + (size_t)(win * LWIN + i) * CDIM + head * HD + 2 * d2) =
            __floats2half2_rn(ox, oy);
    }
}

// ---------------- depthwise 3x3 conv (NHWC) + bias + exact GELU, fp16 I/O ----------------
__global__ __launch_bounds__(256)
void dwconv_gelu(const __half* __restrict__ x, const float* __restrict__ kern,
                 const float* __restrict__ bias, __half* __restrict__ out)
{
    int ch = blockIdx.x * 256 + threadIdx.x;
    int hw = blockIdx.y;
    int b  = blockIdx.z;
    int h = hw / WW, w = hw - h * WW;

    const float* kp = kern + ch * 9;
    float acc = bias[ch];
    size_t brow = (size_t)b * NTOK;
#pragma unroll
    for (int dh = -1; dh <= 1; dh++) {
        int ih = h + dh;
        if ((unsigned)ih >= HH) continue;
#pragma unroll
        for (int dw = -1; dw <= 1; dw++) {
            int iw = w + dw;
            if ((unsigned)iw >= WW) continue;
            acc = fmaf(__half2float(x[(brow + ih * WW + iw) * HID + ch]),
                       kp[(dh + 1) * 3 + (dw + 1)], acc);
        }
    }
    float g = 0.5f * acc * (1.0f + erff(acc * 0.70710678118654752f));
    out[(brow + hw) * HID + ch] = __float2half(g);
}

// ---------------- launcher ----------------
extern "C" void kernel_launch(void* const* d_in, const int* in_sizes, int n_in,
                              void* d_out, int out_size)
{
    const float* x     = (const float*)d_in[0];
    const float* ln1g  = (const float*)d_in[1];
    const float* ln1b  = (const float*)d_in[2];
    const float* qkvw  = (const float*)d_in[3];
    const float* projw = (const float*)d_in[4];
    const float* projb = (const float*)d_in[5];
    const float* ln2g  = (const float*)d_in[6];
    const float* ln2b  = (const float*)d_in[7];
    const float* fc1w  = (const float*)d_in[8];
    const float* fc1b  = (const float*)d_in[9];
    const float* dwk   = (const float*)d_in[10];
    const float* dwb   = (const float*)d_in[11];
    const float* fc2w  = (const float*)d_in[12];
    const float* fc2b  = (const float*)d_in[13];
    float* out = (float*)d_out;

    __half *xw, *qkv, *attn, *xn2, *h1, *h2, *wqkv, *wproj, *wfc1, *wfc2;
    float  *x2;
    cudaGetSymbolAddress((void**)&xw,    g_xw);
    cudaGetSymbolAddress((void**)&qkv,   g_qkv);
    cudaGetSymbolAddress((void**)&attn,  g_attn);
    cudaGetSymbolAddress((void**)&x2,    g_x2);
    cudaGetSymbolAddress((void**)&xn2,   g_xn2);
    cudaGetSymbolAddress((void**)&h1,    g_h1);
    cudaGetSymbolAddress((void**)&h2,    g_h2);
    cudaGetSymbolAddress((void**)&wqkv,  g_wqkv);
    cudaGetSymbolAddress((void**)&wproj, g_wproj);
    cudaGetSymbolAddress((void**)&wfc1,  g_wfc1);
    cudaGetSymbolAddress((void**)&wfc2,  g_wfc2);

    cudaFuncSetAttribute(hgemm<0>, cudaFuncAttributeMaxDynamicSharedMemorySize, GEMM_SMEM);
    cudaFuncSetAttribute(hgemm<1>, cudaFuncAttributeMaxDynamicSharedMemorySize, GEMM_SMEM);
    cudaFuncSetAttribute(hgemm<2>, cudaFuncAttributeMaxDynamicSharedMemorySize, GEMM_SMEM);
    cudaFuncSetAttribute(hgemm<3>, cudaFuncAttributeMaxDynamicSharedMemorySize, GEMM_SMEM);

    // weight prep: fp32 [K,N] -> fp16 [N,K]
    wprep<<<dim3(1152 / 32, 384 / 32),  dim3(32, 8)>>>(qkvw,  wqkv,  384, 1152);
    wprep<<<dim3(384 / 32,  384 / 32),  dim3(32, 8)>>>(projw, wproj, 384, 384);
    wprep<<<dim3(1536 / 32, 384 / 32),  dim3(32, 8)>>>(fc1w,  wfc1,  384, 1536);
    wprep<<<dim3(384 / 32,  1536 / 32), dim3(32, 8)>>>(fc2w,  wfc2,  1536, 384);

    // 1. LN1 + roll(-3,-3) + window partition (fp16 out)
    ln_kernel<true><<<MTOT, 128>>>(x, ln1g, ln1b, xw);
    // 2. QKV GEMM
    hgemm<0><<<dim3(9, 392), 256, GEMM_SMEM>>>(xw, wqkv, qkv, (const float*)0, (const float*)0, CDIM, 3 * CDIM);
    // 3. windowed attention with analytic shift mask
    attn_kernel<<<dim3(1024, HEADS), 256>>>(qkv, attn);
    // 4. proj GEMM + bias + window-reverse scatter + residual(x) -> x2 (fp32)
    hgemm<2><<<dim3(3, 392), 256, GEMM_SMEM>>>(attn, wproj, x2, projb, x, CDIM, CDIM);
    // 5. LN2 (fp16 out)
    ln_kernel<false><<<MTOT, 128>>>(x2, ln2g, ln2b, xn2);
    // 6. fc1 GEMM + bias
    hgemm<1><<<dim3(12, 392), 256, GEMM_SMEM>>>(xn2, wfc1, h1, fc1b, (const float*)0, CDIM, HID);
    // 7. depthwise conv + bias + exact GELU
    dwconv_gelu<<<dim3(6, NTOK, BATCH), 256>>>(h1, dwk, dwb, h2);
    // 8. fc2 GEMM + bias + residual(x2) -> out (fp32)
    hgemm<3><<<dim3(3, 392), 256, GEMM_SMEM>>>(h2, wfc2, out, fc2b, x2, HID, CDIM);
}

// round 5
// speedup vs baseline: 3.9816x; 1.1159x over previous
#include <cuda_runtime.h>
#include <cuda_fp16.h>
#include <math.h>
#include <stdint.h>

// ---------------- problem constants ----------------
#define BATCH 16
#define HH 56
#define WW 56
#define NTOK 3136            // 56*56
#define CDIM 384
#define HEADS 12
#define HD 32
#define WS 7
#define LWIN 49
#define HID 1536
#define MTOT 50176           // BATCH*NTOK = 392*128

// ---------------- scratch (static device memory; no allocations) ----------------
__device__ __align__(256) __half g_xw   [(size_t)MTOT * CDIM];       // LN1 + window partition
__device__ __align__(256) __half g_qkv  [(size_t)MTOT * 3 * CDIM];
__device__ __align__(256) __half g_attn [(size_t)MTOT * CDIM];       // attn out, window order
__device__ __align__(256) float  g_x2   [(size_t)MTOT * CDIM];       // fp32 residual spine
__device__ __align__(256) __half g_xn2  [(size_t)MTOT * CDIM];
__device__ __align__(256) __half g_h1   [(size_t)MTOT * HID];
__device__ __align__(256) __half g_h2   [(size_t)MTOT * HID];
// fp16 transposed weights: Wt[n][k] = W[k][n]
__device__ __align__(256) __half g_wqkv [(size_t)3 * CDIM * CDIM];
__device__ __align__(256) __half g_wproj[(size_t)CDIM * CDIM];
__device__ __align__(256) __half g_wfc1 [(size_t)HID * CDIM];
__device__ __align__(256) __half g_wfc2 [(size_t)CDIM * HID];

// ---------------- helpers ----------------
__device__ __forceinline__ uint32_t smem_u32(const void* p)
{
    uint32_t a;
    asm("{ .reg .u64 t; cvta.to.shared.u64 t, %1; cvt.u32.u64 %0, t; }" : "=r"(a) : "l"(p));
    return a;
}

#define CP_ASYNC16(dst, src) \
    asm volatile("cp.async.cg.shared.global [%0], [%1], 16;" :: "r"(dst), "l"(src))
#define CP_COMMIT() asm volatile("cp.async.commit_group;" ::: "memory")
#define CP_WAIT1()  asm volatile("cp.async.wait_group 1;" ::: "memory")

#define LDSM_X4(r0, r1, r2, r3, addr) \
    asm volatile("ldmatrix.sync.aligned.m8n8.x4.shared.b16 {%0,%1,%2,%3}, [%4];" \
                 : "=r"(r0), "=r"(r1), "=r"(r2), "=r"(r3) : "r"(addr))

#define MMA16816(c, a, b) \
    asm volatile("mma.sync.aligned.m16n8k16.row.col.f32.f16.f16.f32 " \
                 "{%0,%1,%2,%3}, {%4,%5,%6,%7}, {%8,%9}, {%0,%1,%2,%3};" \
                 : "+f"((c)[0]), "+f"((c)[1]), "+f"((c)[2]), "+f"((c)[3]) \
                 : "r"((a)[0]), "r"((a)[1]), "r"((a)[2]), "r"((a)[3]), \
                   "r"((b)[0]), "r"((b)[1]))

// window-order row -> spatial row (window reverse, NO un-shift, per reference)
__device__ __forceinline__ int map_win_to_spatial(int row)
{
    int b  = row / NTOK;
    int t  = row - b * NTOK;
    int wi = t / LWIN;
    int p  = t - wi * LWIN;
    int pr = p / WS;
    int pc = p - pr * WS;
    int h  = (wi >> 3) * WS + pr;
    int w  = (wi & 7)  * WS + pc;
    return b * NTOK + h * WW + w;
}

// ---------------- weight prep: fp32 [K,N] -> fp16 [N,K] (transpose) ----------------
__global__ __launch_bounds__(256)
void wprep(const float* __restrict__ W, __half* __restrict__ Wt, int K, int N)
{
    __shared__ float t[32][33];
    int k0 = blockIdx.y * 32, n0 = blockIdx.x * 32;
    int tx = threadIdx.x, ty = threadIdx.y;   // 32 x 8
#pragma unroll
    for (int i = 0; i < 32; i += 8)
        t[ty + i][tx] = W[(size_t)(k0 + ty + i) * N + n0 + tx];
    __syncthreads();
#pragma unroll
    for (int i = 0; i < 32; i += 8)
        Wt[(size_t)(n0 + ty + i) * K + k0 + tx] = __float2half(t[tx][ty + i]);
}

// ---------------- LayerNorm: warp per row (optionally fused shift + window partition) -------
template <bool SHIFT>
__global__ __launch_bounds__(256)
void ln_kernel(const float* __restrict__ x, const float* __restrict__ g,
               const float* __restrict__ b, __half* __restrict__ out)
{
    const int warp = threadIdx.x >> 5;
    const int lane = threadIdx.x & 31;
    const int row  = blockIdx.x * 8 + warp;
    int srow;
    if (SHIFT) {
        int bb = row / NTOK;
        int t  = row - bb * NTOK;
        int wi = t / LWIN;
        int p  = t - wi * LWIN;
        int pr = p / WS;
        int pc = p - pr * WS;
        int h  = (wi >> 3) * WS + pr + 3; if (h >= HH) h -= HH;
        int w  = (wi & 7)  * WS + pc + 3; if (w >= WW) w -= WW;
        srow = bb * NTOK + h * WW + w;
    } else {
        srow = row;
    }
    const float4* xr = (const float4*)(x + (size_t)srow * CDIM);
    float4 v[3];
    float s = 0.0f, ss = 0.0f;
#pragma unroll
    for (int w = 0; w < 3; w++) {
        v[w] = xr[lane + w * 32];
        s  += v[w].x + v[w].y + v[w].z + v[w].w;
        ss += v[w].x * v[w].x + v[w].y * v[w].y + v[w].z * v[w].z + v[w].w * v[w].w;
    }
#pragma unroll
    for (int off = 16; off; off >>= 1) {
        s  += __shfl_xor_sync(0xffffffffu, s,  off);
        ss += __shfl_xor_sync(0xffffffffu, ss, off);
    }
    const float m   = s * (1.0f / CDIM);
    const float inv = rsqrtf(ss * (1.0f / CDIM) - m * m + 1e-5f);
    uint2* o = (uint2*)(out + (size_t)row * CDIM);
    const float4* gp = (const float4*)g;
    const float4* bp = (const float4*)b;
#pragma unroll
    for (int w = 0; w < 3; w++) {
        float4 gg = gp[lane + w * 32];
        float4 bb = bp[lane + w * 32];
        float o0 = (v[w].x - m) * inv * gg.x + bb.x;
        float o1 = (v[w].y - m) * inv * gg.y + bb.y;
        float o2 = (v[w].z - m) * inv * gg.z + bb.z;
        float o3 = (v[w].w - m) * inv * gg.w + bb.w;
        uint2 u;
        ((__half2*)&u)[0] = __floats2half2_rn(o0, o1);
        ((__half2*)&u)[1] = __floats2half2_rn(o2, o3);
        o[lane + w * 32] = u;
    }
}

// ---------------- fp16 HMMA GEMM: C(MxN) = A(MxK) * Bw(NxK)^T, fp32 accumulate -------------
// Tile 128x128x64, 3-stage cp.async pipeline, 2 CTAs/SM, compile-time K/N.
// MODE 0: C fp16, no bias    MODE 1: C fp16 + bias
// MODE 2: C fp32 + bias + win->spatial scatter + residual
// MODE 3: C fp32 + bias + residual (same row)
#define BMM 128
#define BNN 128
#define BKK 64
#define STG 3
#define STG_BYTES 16384                   // 128 rows * 128 B
#define GEMM_SMEM (STG * 2 * STG_BYTES)   // 98304

template <int MODE, int K, int N>
__global__ __launch_bounds__(256, 2)
void hgemm(const __half* __restrict__ A, const __half* __restrict__ Bw,
           void* __restrict__ Cout, const float* __restrict__ bias,
           const float* __restrict__ resid)
{
    extern __shared__ char smem[];
    const uint32_t sA = smem_u32(smem);
    const uint32_t sB = sA + STG * STG_BYTES;

    const int tid  = threadIdx.x;
    const int wid  = tid >> 5;
    const int lane = tid & 31;
    const int bm   = blockIdx.y * BMM;
    const int bn   = blockIdx.x * BNN;
    const int wm0  = (wid & 3) * 32;   // warp row offset in tile
    const int wn0  = (wid >> 2) * 64;  // warp col offset in tile

    // global load mapping: 1024 16B-chunks per tile (A or B), 4 per thread each
    const int lc = tid & 7;
    int   lrow[4];
    uint32_t so[4];
#pragma unroll
    for (int q = 0; q < 4; q++) {
        lrow[q] = (tid + q * 256) >> 3;
        so[q]   = (uint32_t)lrow[q] * 128 + (uint32_t)((lc ^ (lrow[q] & 7)) << 4);
    }

    constexpr int NC = K / BKK;

    // prologue: stages 0,1
#pragma unroll
    for (int c = 0; c < 2; c++) {
        const __half* Ag = A  + (size_t)bm * K + c * BKK;
        const __half* Bg = Bw + (size_t)bn * K + c * BKK;
        uint32_t da = sA + c * STG_BYTES;
        uint32_t db = sB + c * STG_BYTES;
#pragma unroll
        for (int q = 0; q < 4; q++) {
            CP_ASYNC16(da + so[q], Ag + (size_t)lrow[q] * K + lc * 8);
            CP_ASYNC16(db + so[q], Bg + (size_t)lrow[q] * K + lc * 8);
        }
        CP_COMMIT();
    }

    float acc[2][8][4];
#pragma unroll
    for (int i = 0; i < 2; i++)
#pragma unroll
        for (int j = 0; j < 8; j++)
#pragma unroll
            for (int r = 0; r < 4; r++) acc[i][j][r] = 0.0f;

    // per-lane ldmatrix row/chunk components
    const int a_row_l = (lane & 8) + (lane & 7);                // + fi*16
    const int a_chk_l = (lane >> 4) & 1;                        // + 2*ks
    const int b_row_l = (((lane >> 4) & 1) << 3) + (lane & 7);  // + nj*16
    const int b_chk_l = (lane >> 3) & 1;                        // + 2*ks

    for (int c = 0; c < NC; c++) {
        const int st = c % STG;
        CP_WAIT1();
        __syncthreads();   // single barrier: orders stage-c reads of ALL warps
                           // before anyone prefetches into stage (c+2)%3 next iter

        if (c + 2 < NC) {
            const int cc = c + 2, s2 = cc % STG;
            const __half* Ag = A  + (size_t)bm * K + cc * BKK;
            const __half* Bg = Bw + (size_t)bn * K + cc * BKK;
            uint32_t da = sA + s2 * STG_BYTES;
            uint32_t db = sB + s2 * STG_BYTES;
#pragma unroll
            for (int q = 0; q < 4; q++) {
                CP_ASYNC16(da + so[q], Ag + (size_t)lrow[q] * K + lc * 8);
                CP_ASYNC16(db + so[q], Bg + (size_t)lrow[q] * K + lc * 8);
            }
        }
        CP_COMMIT();

        const uint32_t ab = sA + st * STG_BYTES;
        const uint32_t bb = sB + st * STG_BYTES;
#pragma unroll
        for (int ks = 0; ks < 4; ks++) {
            uint32_t a[2][4], b[8][2];
#pragma unroll
            for (int fi = 0; fi < 2; fi++) {
                int row = wm0 + fi * 16 + a_row_l;
                int chk = 2 * ks + a_chk_l;
                uint32_t ad = ab + (uint32_t)row * 128 + (uint32_t)((chk ^ (row & 7)) << 4);
                LDSM_X4(a[fi][0], a[fi][1], a[fi][2], a[fi][3], ad);
            }
#pragma unroll
            for (int nj = 0; nj < 4; nj++) {
                int row = wn0 + nj * 16 + b_row_l;
                int chk = 2 * ks + b_chk_l;
                uint32_t bd = bb + (uint32_t)row * 128 + (uint32_t)((chk ^ (row & 7)) << 4);
                LDSM_X4(b[nj * 2][0], b[nj * 2][1], b[nj * 2 + 1][0], b[nj * 2 + 1][1], bd);
            }
#pragma unroll
            for (int fi = 0; fi < 2; fi++)
#pragma unroll
                for (int j = 0; j < 8; j++)
                    MMA16816(acc[fi][j], a[fi], b[j]);
        }
    }

    // ---------------- epilogue ----------------
#pragma unroll
    for (int fi = 0; fi < 2; fi++) {
#pragma unroll
        for (int h = 0; h < 2; h++) {
            int row  = bm + wm0 + fi * 16 + (lane >> 2) + h * 8;
            int orow = (MODE == 2) ? map_win_to_spatial(row) : row;
#pragma unroll
            for (int j = 0; j < 8; j++) {
                int col = bn + wn0 + j * 8 + (lane & 3) * 2;
                float v0 = acc[fi][j][h * 2];
                float v1 = acc[fi][j][h * 2 + 1];
                if (MODE >= 1) { v0 += bias[col]; v1 += bias[col + 1]; }
                if (MODE >= 2) {
                    const float* rp = resid + (size_t)orow * N + col;
                    float2 rr = *(const float2*)rp;
                    float2 o; o.x = v0 + rr.x; o.y = v1 + rr.y;
                    *(float2*)((float*)Cout + (size_t)orow * N + col) = o;
                } else {
                    *(__half2*)((__half*)Cout + (size_t)row * N + col) =
                        __floats2half2_rn(v0, v1);
                }
            }
        }
    }
}

// ---------------- windowed attention: one block per (window, head), half2-resident --------
__global__ __launch_bounds__(256)
void attn_kernel(const __half* __restrict__ qkv, __half* __restrict__ out)
{
    const int win  = blockIdx.x;
    const int head = blockIdx.y;
    const int tid  = threadIdx.x;

    __shared__ __half2 qh[LWIN * 17];
    __shared__ __half2 kh[LWIN * 17];
    __shared__ __half2 vh[LWIN * 17];
    __shared__ float   sc[LWIN * 52];
    __shared__ int     rg[LWIN];

    const float scale = 0.17677669529663687f;  // 1/sqrt(32)
    const size_t base = (size_t)win * LWIN * (3 * CDIM) + head * HD;

    for (int idx = tid; idx < LWIN * 16; idx += 256) {
        int p = idx >> 4, d2 = idx & 15;
        const __half2* r = (const __half2*)(qkv + base + (size_t)p * (3 * CDIM));
        qh[p * 17 + d2] = r[d2];
        kh[p * 17 + d2] = r[CDIM / 2 + d2];
        vh[p * 17 + d2] = r[CDIM + d2];
    }
    if (tid < LWIN) {
        int wi = win & 63;
        int h = (wi >> 3) * WS + tid / WS;
        int w = (wi & 7)  * WS + tid % WS;
        int sh = (h < HH - WS) ? 0 : ((h < HH - 3) ? 1 : 2);
        int sw = (w < WW - WS) ? 0 : ((w < WW - 3) ? 1 : 2);
        rg[tid] = sh * 3 + sw;
    }
    __syncthreads();

    // scores = (q @ k^T) * scale + mask
    for (int idx = tid; idx < LWIN * LWIN; idx += 256) {
        int i = idx / LWIN, j = idx - i * LWIN;
        float s = 0.0f;
#pragma unroll
        for (int d2 = 0; d2 < 16; d2++) {
            float2 a = __half22float2(qh[i * 17 + d2]);
            float2 b = __half22float2(kh[j * 17 + d2]);
            s = fmaf(a.x, b.x, s);
            s = fmaf(a.y, b.y, s);
        }
        s *= scale;
        if (rg[i] != rg[j]) s -= 100.0f;
        sc[i * 52 + j] = s;
    }
    __syncthreads();

    // softmax rows (one warp per row)
    int wid = tid >> 5, lane = tid & 31;
    for (int i = wid; i < LWIN; i += 8) {
        float v0 = (lane < LWIN)      ? sc[i * 52 + lane]      : -1e30f;
        float v1 = (lane + 32 < LWIN) ? sc[i * 52 + lane + 32] : -1e30f;
        float m = fmaxf(v0, v1);
#pragma unroll
        for (int off = 16; off; off >>= 1) m = fmaxf(m, __shfl_xor_sync(0xffffffffu, m, off));
        float e0 = (lane < LWIN)      ? __expf(v0 - m) : 0.0f;
        float e1 = (lane + 32 < LWIN) ? __expf(v1 - m) : 0.0f;
        float s = e0 + e1;
#pragma unroll
        for (int off = 16; off; off >>= 1) s += __shfl_xor_sync(0xffffffffu, s, off);
        float r = 1.0f / s;
        if (lane < LWIN)      sc[i * 52 + lane]      = e0 * r;
        if (lane + 32 < LWIN) sc[i * 52 + lane + 32] = e1 * r;
    }
    __syncthreads();

    // out = softmax @ v
    for (int idx = tid; idx < LWIN * 16; idx += 256) {
        int i = idx >> 4, d2 = idx & 15;
        float ox = 0.0f, oy = 0.0f;
#pragma unroll 7
        for (int j = 0; j < LWIN; j++) {
            float p = sc[i * 52 + j];
            float2 v = __half22float2(vh[j * 17 + d2]);
            ox = fmaf(p, v.x, ox);
            oy = fmaf(p, v.y, oy);
        }
        *(__half2*)(out + (size_t)(win * LWIN + i) * CDIM + head * HD + 2 * d2) =
            __floats2half2_rn(ox, oy);
    }
}

// ---------------- depthwise 3x3 conv (NHWC, half2: 2 channels/thread) + bias + GELU --------
__global__ __launch_bounds__(256)
void dwconv_gelu(const __half* __restrict__ x, const float* __restrict__ kern,
                 const float* __restrict__ bias, __half* __restrict__ out)
{
    int c2 = blockIdx.x * 256 + threadIdx.x;   // 0..767 (pair index)
    int ch = c2 * 2;
    int hw = blockIdx.y;
    int b  = blockIdx.z;
    int h = hw / WW, w = hw - h * WW;

    const float* kp0 = kern + ch * 9;
    const float* kp1 = kern + ch * 9 + 9;
    float2 bb = *(const float2*)(bias + ch);
    float a0 = bb.x, a1 = bb.y;
    size_t brow = (size_t)b * NTOK;
#pragma unroll
    for (int dh = -1; dh <= 1; dh++) {
        int ih = h + dh;
        if ((unsigned)ih >= HH) continue;
#pragma unroll
        for (int dw = -1; dw <= 1; dw++) {
            int iw = w + dw;
            if ((unsigned)iw >= WW) continue;
            float2 v = __half22float2(*(const __half2*)(x + (brow + ih * WW + iw) * HID + ch));
            int ki = (dh + 1) * 3 + (dw + 1);
            a0 = fmaf(v.x, kp0[ki], a0);
            a1 = fmaf(v.y, kp1[ki], a1);
        }
    }
    float g0 = 0.5f * a0 * (1.0f + erff(a0 * 0.70710678118654752f));
    float g1 = 0.5f * a1 * (1.0f + erff(a1 * 0.70710678118654752f));
    *(__half2*)(out + (brow + hw) * HID + ch) = __floats2half2_rn(g0, g1);
}

// ---------------- launcher ----------------
extern "C" void kernel_launch(void* const* d_in, const int* in_sizes, int n_in,
                              void* d_out, int out_size)
{
    const float* x     = (const float*)d_in[0];
    const float* ln1g  = (const float*)d_in[1];
    const float* ln1b  = (const float*)d_in[2];
    const float* qkvw  = (const float*)d_in[3];
    const float* projw = (const float*)d_in[4];
    const float* projb = (const float*)d_in[5];
    const float* ln2g  = (const float*)d_in[6];
    const float* ln2b  = (const float*)d_in[7];
    const float* fc1w  = (const float*)d_in[8];
    const float* fc1b  = (const float*)d_in[9];
    const float* dwk   = (const float*)d_in[10];
    const float* dwb   = (const float*)d_in[11];
    const float* fc2w  = (const float*)d_in[12];
    const float* fc2b  = (const float*)d_in[13];
    float* out = (float*)d_out;

    __half *xw, *qkv, *attn, *xn2, *h1, *h2, *wqkv, *wproj, *wfc1, *wfc2;
    float  *x2;
    cudaGetSymbolAddress((void**)&xw,    g_xw);
    cudaGetSymbolAddress((void**)&qkv,   g_qkv);
    cudaGetSymbolAddress((void**)&attn,  g_attn);
    cudaGetSymbolAddress((void**)&x2,    g_x2);
    cudaGetSymbolAddress((void**)&xn2,   g_xn2);
    cudaGetSymbolAddress((void**)&h1,    g_h1);
    cudaGetSymbolAddress((void**)&h2,    g_h2);
    cudaGetSymbolAddress((void**)&wqkv,  g_wqkv);
    cudaGetSymbolAddress((void**)&wproj, g_wproj);
    cudaGetSymbolAddress((void**)&wfc1,  g_wfc1);
    cudaGetSymbolAddress((void**)&wfc2,  g_wfc2);

    cudaFuncSetAttribute(hgemm<0, CDIM, 3 * CDIM>, cudaFuncAttributeMaxDynamicSharedMemorySize, GEMM_SMEM);
    cudaFuncSetAttribute(hgemm<2, CDIM, CDIM>,     cudaFuncAttributeMaxDynamicSharedMemorySize, GEMM_SMEM);
    cudaFuncSetAttribute(hgemm<1, CDIM, HID>,      cudaFuncAttributeMaxDynamicSharedMemorySize, GEMM_SMEM);
    cudaFuncSetAttribute(hgemm<3, HID, CDIM>,      cudaFuncAttributeMaxDynamicSharedMemorySize, GEMM_SMEM);

    // weight prep: fp32 [K,N] -> fp16 [N,K]
    wprep<<<dim3(1152 / 32, 384 / 32),  dim3(32, 8)>>>(qkvw,  wqkv,  384, 1152);
    wprep<<<dim3(384 / 32,  384 / 32),  dim3(32, 8)>>>(projw, wproj, 384, 384);
    wprep<<<dim3(1536 / 32, 384 / 32),  dim3(32, 8)>>>(fc1w,  wfc1,  384, 1536);
    wprep<<<dim3(384 / 32,  1536 / 32), dim3(32, 8)>>>(fc2w,  wfc2,  1536, 384);

    // 1. LN1 + roll(-3,-3) + window partition (fp16 out)
    ln_kernel<true><<<MTOT / 8, 256>>>(x, ln1g, ln1b, xw);
    // 2. QKV GEMM
    hgemm<0, CDIM, 3 * CDIM><<<dim3(9, 392), 256, GEMM_SMEM>>>(xw, wqkv, qkv, (const float*)0, (const float*)0);
    // 3. windowed attention with analytic shift mask
    attn_kernel<<<dim3(1024, HEADS), 256>>>(qkv, attn);
    // 4. proj GEMM + bias + window-reverse scatter + residual(x) -> x2 (fp32)
    hgemm<2, CDIM, CDIM><<<dim3(3, 392), 256, GEMM_SMEM>>>(attn, wproj, x2, projb, x);
    // 5. LN2 (fp16 out)
    ln_kernel<false><<<MTOT / 8, 256>>>(x2, ln2g, ln2b, xn2);
    // 6. fc1 GEMM + bias
    hgemm<1, CDIM, HID><<<dim3(12, 392), 256, GEMM_SMEM>>>(xn2, wfc1, h1, fc1b, (const float*)0);
    // 7. depthwise conv + bias + exact GELU (half2)
    dwconv_gelu<<<dim3(3, NTOK, BATCH), 256>>>(h1, dwk, dwb, h2);
    // 8. fc2 GEMM + bias + residual(x2) -> out (fp32)
    hgemm<3, HID, CDIM><<<dim3(3, 392), 256, GEMM_SMEM>>>(h2, wfc2, out, fc2b, x2);
}